// round 5
// baseline (speedup 1.0000x reference)
#include <cuda_runtime.h>
#include <cstdint>

#define NQ   512
#define SS   2048
#define DD   128
#define TOPK 32
#define CLS  1000

__device__ float g_summary[NQ * DD];

__device__ __forceinline__ float warp_sum(float v) {
    #pragma unroll
    for (int o = 16; o > 0; o >>= 1) v += __shfl_xor_sync(0xffffffffu, v, o);
    return v;
}

__device__ __forceinline__ void cp_async16(void* smem, const void* gmem) {
    uint32_t s = (uint32_t)__cvta_generic_to_shared(smem);
    asm volatile("cp.async.cg.shared.global [%0], [%1], 16;" :: "r"(s), "l"(gmem));
}

// ---------------------------------------------------------------------------
// Fused attention: stream K (warp-autonomous cp.async pipelines, no block
// barriers), logits -> smem, hierarchical top-32, softmax, V gather,
// weights row composed in smem and streamed out.
// grid = 512 (one CTA per query); ~43KB smem -> all CTAs resident in wave 1.
// ---------------------------------------------------------------------------
__global__ __launch_bounds__(256, 4) void attn_topk_kernel(
    const float* __restrict__ q,
    const float* __restrict__ Kmat,
    const float* __restrict__ Vmat,
    float* __restrict__ weights_out)
{
    const int n    = blockIdx.x;
    const int tid  = threadIdx.x;
    const int warp = tid >> 5;
    const int lane = tid & 31;
    const int row4 = lane >> 3;   // 0..3 row within 4-row tile
    const int g    = lane & 7;    // 0..7 group within row

    __shared__ __align__(16) float kring[8][2][4 * DD];   // 32 KB
    __shared__ float logits[SS];                          // 8 KB
    __shared__ float cand_v[256];
    __shared__ int   cand_i[256];
    __shared__ float s_topv[TOPK];
    __shared__ int   s_topi[TOPK];
    __shared__ float s_w[TOPK];

    const float NEG_INF = __int_as_float(0xff800000);
    const float scale   = 0.08838834764831845f; // 1/sqrt(128)

    // q fragment: floats {g*4 + j*32 .. +3}
    float4 qf[4];
    {
        const float* qrow = q + (size_t)n * DD;
        #pragma unroll
        for (int j = 0; j < 4; j++)
            qf[j] = *reinterpret_cast<const float4*>(qrow + g * 4 + j * 32);
    }

    // this warp's 256 seq rows, processed as 64 tiles of 4 rows
    const float* __restrict__ Ksrc = Kmat + ((size_t)n * SS + warp * 256) * DD;
    float* __restrict__ lwarp = logits + warp * 256;

    #define K1_ISSUE(t)                                                        \
        do {                                                                   \
            float* _dst = kring[warp][(t) & 1];                                \
            const float* _src = Ksrc + (size_t)(t) * 4 * DD;                   \
            _Pragma("unroll")                                                  \
            for (int _i = 0; _i < 4; _i++)                                     \
                cp_async16(&_dst[(lane + 32 * _i) * 4],                        \
                           _src + (lane + 32 * _i) * 4);                       \
            asm volatile("cp.async.commit_group;");                            \
        } while (0)

    K1_ISSUE(0);
    K1_ISSUE(1);

    #pragma unroll 1
    for (int t = 0; t < 64; t++) {
        if (t + 1 < 64) asm volatile("cp.async.wait_group 1;");
        else            asm volatile("cp.async.wait_group 0;");
        __syncwarp();   // tile t visible to all lanes

        const float* kb = &kring[warp][t & 1][row4 * DD];
        float p = 0.f;
        #pragma unroll
        for (int j = 0; j < 4; j++) {
            float4 kv = *reinterpret_cast<const float4*>(kb + g * 4 + j * 32);
            p += qf[j].x * kv.x + qf[j].y * kv.y + qf[j].z * kv.z + qf[j].w * kv.w;
        }
        p += __shfl_xor_sync(0xffffffffu, p, 1);
        p += __shfl_xor_sync(0xffffffffu, p, 2);
        p += __shfl_xor_sync(0xffffffffu, p, 4);
        if (g == 0) lwarp[t * 4 + row4] = p * scale;
        __syncwarp();   // tile t consumed; slot reusable

        if (t + 2 < 64) K1_ISSUE(t + 2);
    }
    #undef K1_ISSUE
    __syncthreads();

    // ---- per-warp top-32 of its 256 logits (barrier-free) ----
    {
        float r[8];
        const int base = warp * 256 + lane;
        #pragma unroll
        for (int j = 0; j < 8; j++) r[j] = logits[base + j * 32];

        #pragma unroll 1
        for (int k = 0; k < TOPK; k++) {
            float bv = r[0]; int bj = 0;
            #pragma unroll
            for (int j = 1; j < 8; j++)
                if (r[j] > bv) { bv = r[j]; bj = j; }
            int bi = warp * 256 + bj * 32 + lane;
            #pragma unroll
            for (int o = 16; o > 0; o >>= 1) {
                float ov = __shfl_xor_sync(0xffffffffu, bv, o);
                int   oi = __shfl_xor_sync(0xffffffffu, bi, o);
                if (ov > bv || (ov == bv && oi < bi)) { bv = ov; bi = oi; }
            }
            if (lane == (bi & 31)) {
                int jw = (bi >> 5) & 7;
                #pragma unroll
                for (int j = 0; j < 8; j++)
                    if (j == jw) r[j] = NEG_INF;
            }
            if (lane == 0) { cand_v[warp * 32 + k] = bv; cand_i[warp * 32 + k] = bi; }
        }
    }
    __syncthreads();

    // ---- warp 0: merge 256 candidates -> top-32; softmax ----
    if (warp == 0) {
        float cv[8];
        #pragma unroll
        for (int j = 0; j < 8; j++) cv[j] = cand_v[j * 32 + lane];

        #pragma unroll 1
        for (int k = 0; k < TOPK; k++) {
            float bv = cv[0]; int bj = 0;
            #pragma unroll
            for (int j = 1; j < 8; j++)
                if (cv[j] > bv) { bv = cv[j]; bj = j; }
            int bp = bj * 32 + lane;   // position order == index order on ties
            #pragma unroll
            for (int o = 16; o > 0; o >>= 1) {
                float ov = __shfl_xor_sync(0xffffffffu, bv, o);
                int   op = __shfl_xor_sync(0xffffffffu, bp, o);
                if (ov > bv || (ov == bv && op < bp)) { bv = ov; bp = op; }
            }
            if (lane == (bp & 31)) {
                int jw = bp >> 5;
                #pragma unroll
                for (int j = 0; j < 8; j++)
                    if (j == jw) cv[j] = NEG_INF;
            }
            if (lane == 0) { s_topv[k] = bv; s_topi[k] = cand_i[bp]; }
        }
        __syncwarp();

        float v = s_topv[lane];
        float m = s_topv[0];          // first extraction == global max
        float e = expf(v - m);
        float denom = warp_sum(e);
        s_w[lane] = e / denom;
    }
    __syncthreads();

    // ---- V gather while zeroing the logits buffer ----
    float acc = 0.f;
    if (tid < DD) {
        #pragma unroll
        for (int i = 0; i < TOPK; i++)
            acc += s_w[i] * Vmat[((size_t)n * SS + s_topi[i]) * DD + tid];
    }
    {
        float4 z = make_float4(0.f, 0.f, 0.f, 0.f);
        float4* l4 = reinterpret_cast<float4*>(logits);
        #pragma unroll
        for (int i = tid; i < SS / 4; i += 256) l4[i] = z;
    }
    __syncthreads();

    if (tid < TOPK) logits[s_topi[tid]] = s_w[tid];
    if (tid < DD)   g_summary[n * DD + tid] = acc;
    __syncthreads();

    // stream the composed weights row out (coalesced, single write)
    {
        const float4* src = reinterpret_cast<const float4*>(logits);
        float4* dst = reinterpret_cast<float4*>(weights_out + (size_t)n * SS);
        #pragma unroll
        for (int i = tid; i < SS / 4; i += 256) dst[i] = src[i];
    }
}

// ---------------------------------------------------------------------------
// Fused readout GEMMs: out[n,c] = sum_d summary[n,d]*W[c,d] + bias[c]
// 32x32 tiles, full K=128 in smem (one barrier), 2x2 micro-tile.
// grid (36, 16): bx<32 -> cls (C=1000), bx 32..35 -> rec (C=128).
// ---------------------------------------------------------------------------
__global__ __launch_bounds__(256) void readout_gemm(
    const float* __restrict__ Wc, const float* __restrict__ bc, float* __restrict__ outc,
    const float* __restrict__ Wr, const float* __restrict__ br, float* __restrict__ outr)
{
    const float* W;  const float* bias;  float* out;  int C;  int cTile;
    if (blockIdx.x < 32) { W = Wc; bias = bc; out = outc; C = CLS; cTile = blockIdx.x * 32; }
    else                 { W = Wr; bias = br; out = outr; C = DD;  cTile = (blockIdx.x - 32) * 32; }

    const int tid = threadIdx.x;
    const int tx  = tid & 15;       // c pair
    const int ty  = tid >> 4;       // n pair
    const int nTile = blockIdx.y * 32;

    __shared__ __align__(16) float As[DD][34];   // [k][n], even stride for float2
    __shared__ __align__(16) float Bs[DD][34];   // [k][c]

    // load: 32 rows x 128 k per matrix; 16 floats (4 float4) per thread
    {
        const int rr  = tid >> 3;   // 0..31
        const int k16 = tid & 7;    // 0..7
        const float* aRow = g_summary + (size_t)(nTile + rr) * DD + k16 * 16;
        const int cg = cTile + rr;
        const float* bRow = W + (size_t)cg * DD + k16 * 16;
        #pragma unroll
        for (int j = 0; j < 4; j++) {
            float4 va = *reinterpret_cast<const float4*>(aRow + j * 4);
            int kb = k16 * 16 + j * 4;
            As[kb + 0][rr] = va.x;
            As[kb + 1][rr] = va.y;
            As[kb + 2][rr] = va.z;
            As[kb + 3][rr] = va.w;
            float4 vb = make_float4(0.f, 0.f, 0.f, 0.f);
            if (cg < C) vb = *reinterpret_cast<const float4*>(bRow + j * 4);
            Bs[kb + 0][rr] = vb.x;
            Bs[kb + 1][rr] = vb.y;
            Bs[kb + 2][rr] = vb.z;
            Bs[kb + 3][rr] = vb.w;
        }
    }
    __syncthreads();

    float acc00 = 0.f, acc01 = 0.f, acc10 = 0.f, acc11 = 0.f;
    #pragma unroll 16
    for (int kk = 0; kk < DD; kk++) {
        float2 a = *reinterpret_cast<const float2*>(&As[kk][ty * 2]);
        float2 b = *reinterpret_cast<const float2*>(&Bs[kk][tx * 2]);
        acc00 += a.x * b.x;
        acc01 += a.x * b.y;
        acc10 += a.y * b.x;
        acc11 += a.y * b.y;
    }

    const int n0 = nTile + ty * 2;
    const int c0 = cTile + tx * 2;
    if (c0 + 0 < C) {
        float bb = bias[c0];
        out[(size_t)(n0 + 0) * C + c0] = acc00 + bb;
        out[(size_t)(n0 + 1) * C + c0] = acc10 + bb;
    }
    if (c0 + 1 < C) {
        float bb = bias[c0 + 1];
        out[(size_t)(n0 + 0) * C + c0 + 1] = acc01 + bb;
        out[(size_t)(n0 + 1) * C + c0 + 1] = acc11 + bb;
    }
}

extern "C" void kernel_launch(void* const* d_in, const int* in_sizes, int n_in,
                              void* d_out, int out_size) {
    const float* q     = (const float*)d_in[0];
    const float* Kmat  = (const float*)d_in[1];
    const float* Vmat  = (const float*)d_in[2];
    const float* W_cls = (const float*)d_in[3];
    const float* b_cls = (const float*)d_in[4];
    const float* W_rec = (const float*)d_in[5];
    const float* b_rec = (const float*)d_in[6];

    float* out = (float*)d_out;
    float* cls = out;
    float* rec = out + (size_t)NQ * CLS;
    float* wts = rec + (size_t)NQ * DD;

    attn_topk_kernel<<<NQ, 256>>>(q, Kmat, Vmat, wts);
    readout_gemm<<<dim3(36, NQ / 32), 256>>>(W_cls, b_cls, cls, W_rec, b_rec, rec);
}

// round 7
// speedup vs baseline: 1.2368x; 1.2368x over previous
#include <cuda_runtime.h>
#include <cstdint>

#define NQ   512
#define SS   2048
#define DD   128
#define TOPK 32
#define CLS  1000

__device__ float g_summary[NQ * DD];

__device__ __forceinline__ float warp_sum(float v) {
    #pragma unroll
    for (int o = 16; o > 0; o >>= 1) v += __shfl_xor_sync(0xffffffffu, v, o);
    return v;
}

__device__ __forceinline__ void cp_async16(void* smem, const void* gmem) {
    uint32_t s = (uint32_t)__cvta_generic_to_shared(smem);
    asm volatile("cp.async.cg.shared.global [%0], [%1], 16;" :: "r"(s), "l"(gmem));
}

// monotone map: float total order == uint32 order. no NaNs in this data.
__device__ __forceinline__ uint32_t fmono(float x) {
    uint32_t b = __float_as_uint(x);
    return (b & 0x80000000u) ? ~b : (b | 0x80000000u);
}

// ---------------------------------------------------------------------------
// Fused: K streaming (warp-autonomous cp.async, no block barriers) -> logits,
// radix-select top-32 (4x8-bit rounds), softmax, V gather, weights row.
// grid = 512; ~47KB smem -> 4 CTAs/SM, all resident in wave 1.
// ---------------------------------------------------------------------------
__global__ __launch_bounds__(256) void attn_topk_kernel(
    const float* __restrict__ q,
    const float* __restrict__ Kmat,
    const float* __restrict__ Vmat,
    float* __restrict__ weights_out)
{
    const int n    = blockIdx.x;
    const int tid  = threadIdx.x;
    const int warp = tid >> 5;
    const int lane = tid & 31;
    const int row4 = lane >> 3;
    const int g    = lane & 7;

    __shared__ __align__(16) float kring[8][2][4 * DD];  // 32 KB
    __shared__ float logits[SS];                         // 8 KB
    __shared__ uint32_t hist[4][256];                    // 4 KB
    __shared__ uint32_t sge[256];                        // 1 KB
    __shared__ uint32_t wsum[8];
    __shared__ int   s_topi[TOPK];
    __shared__ float s_w[TOPK];
    __shared__ int   eqbuf[64];
    __shared__ uint32_t s_prefix;
    __shared__ int   s_need, cA, cE;

    const float scale = 0.08838834764831845f; // 1/sqrt(128)

    // q fragment: floats {g*4 + j*32 .. +3}
    float4 qf[4];
    {
        const float* qrow = q + (size_t)n * DD;
        #pragma unroll
        for (int j = 0; j < 4; j++)
            qf[j] = *reinterpret_cast<const float4*>(qrow + g * 4 + j * 32);
    }

    const float* __restrict__ Ksrc = Kmat + ((size_t)n * SS + warp * 256) * DD;
    float* __restrict__ lwarp = logits + warp * 256;

    #define K1_ISSUE(t)                                                        \
        do {                                                                   \
            float* _dst = kring[warp][(t) & 1];                                \
            const float* _src = Ksrc + (size_t)(t) * 4 * DD;                   \
            _Pragma("unroll")                                                  \
            for (int _i = 0; _i < 4; _i++)                                     \
                cp_async16(&_dst[(lane + 32 * _i) * 4],                        \
                           _src + (lane + 32 * _i) * 4);                       \
            asm volatile("cp.async.commit_group;");                            \
        } while (0)

    K1_ISSUE(0);
    K1_ISSUE(1);

    #pragma unroll 1
    for (int t = 0; t < 64; t++) {
        if (t + 1 < 64) asm volatile("cp.async.wait_group 1;");
        else            asm volatile("cp.async.wait_group 0;");
        __syncwarp();

        const float* kb = &kring[warp][t & 1][row4 * DD];
        float p = 0.f;
        #pragma unroll
        for (int j = 0; j < 4; j++) {
            float4 kv = *reinterpret_cast<const float4*>(kb + g * 4 + j * 32);
            p += qf[j].x * kv.x + qf[j].y * kv.y + qf[j].z * kv.z + qf[j].w * kv.w;
        }
        p += __shfl_xor_sync(0xffffffffu, p, 1);
        p += __shfl_xor_sync(0xffffffffu, p, 2);
        p += __shfl_xor_sync(0xffffffffu, p, 4);
        if (g == 0) lwarp[t * 4 + row4] = p * scale;
        __syncwarp();

        if (t + 2 < 64) K1_ISSUE(t + 2);
    }
    #undef K1_ISSUE

    if (tid == 0) { s_prefix = 0; s_need = TOPK; cA = 0; cE = 0; }
    __syncthreads();

    // cache this thread's 8 logits as monotone uints (indices tid + 256*j)
    uint32_t u[8];
    #pragma unroll
    for (int j = 0; j < 8; j++) u[j] = fmono(logits[tid + 256 * j]);

    // ---- radix select: 4 rounds of 8 bits, MSB first ----
    #pragma unroll 1
    for (int r = 0; r < 4; r++) {
        const int sh = 24 - 8 * r;
        // FIX: complete clear — every thread zeroes its column in all 4 banks
        #pragma unroll
        for (int b = 0; b < 4; b++) hist[b][tid] = 0;
        __syncthreads();
        const uint32_t pfx  = s_prefix;
        const int      need = s_need;
        #pragma unroll
        for (int j = 0; j < 8; j++) {
            uint32_t uu = u[j];
            bool ok = (r == 0) || ((uu >> (sh + 8)) == pfx);
            if (ok) atomicAdd(&hist[warp & 3][(uu >> sh) & 255u], 1u);
        }
        __syncthreads();
        // total count for bucket = tid; warp suffix-sum + higher-warp tails
        uint32_t v = hist[0][tid] + hist[1][tid] + hist[2][tid] + hist[3][tid];
        #pragma unroll
        for (int o = 1; o < 32; o <<= 1) {
            uint32_t t2 = __shfl_down_sync(0xffffffffu, v, o);
            if (lane + o < 32) v += t2;
        }
        if (lane == 0) wsum[warp] = v;
        __syncthreads();
        uint32_t tail = 0;
        #pragma unroll
        for (int w = 0; w < 8; w++) if (w > warp) tail += wsum[w];
        uint32_t ge = v + tail;      // count of elements with byte >= tid
        sge[tid] = ge;
        __syncthreads();
        uint32_t ge_next = (tid == 255) ? 0u : sge[tid + 1];
        if (ge >= (uint32_t)need && ge_next < (uint32_t)need) {  // unique tid
            s_prefix = (pfx << 8) | (uint32_t)tid;
            s_need   = need - (int)ge_next;
        }
        __syncthreads();
    }

    const uint32_t ustar  = s_prefix;   // exact 32-bit image of the kth value
    const int      needEq = s_need;     // >=1 ties at ustar to take

    // ---- collect: all strictly greater, plus lowest-index equals ----
    #pragma unroll
    for (int j = 0; j < 8; j++) {
        uint32_t uu = u[j];
        if (uu > ustar) {
            int p = atomicAdd(&cA, 1);
            if (p < TOPK) s_topi[p] = tid + 256 * j;   // defensive bound
        } else if (uu == ustar) {
            int p = atomicAdd(&cE, 1);
            if (p < 64) eqbuf[p] = tid + 256 * j;
        }
    }
    __syncthreads();

    if (warp == 0) {
        const int m = min(cA, TOPK - needEq);
        int E = min(cE, 64);
        int a  = (lane      < E) ? eqbuf[lane]      : 0x7FFFFFFF;
        int b2 = (lane + 32 < E) ? eqbuf[lane + 32] : 0x7FFFFFFF;
        #pragma unroll 1
        for (int t = 0; t < needEq; t++) {
            int mn = min(a, b2);
            #pragma unroll
            for (int o = 16; o > 0; o >>= 1)
                mn = min(mn, __shfl_xor_sync(0xffffffffu, mn, o));
            if (a == mn)       a  = 0x7FFFFFFF;
            else if (b2 == mn) b2 = 0x7FFFFFFF;
            if (lane == 0) s_topi[m + t] = mn;
        }
        __syncwarp();

        // softmax over the 32 kept
        float val = logits[s_topi[lane]];
        float mx = val;
        #pragma unroll
        for (int o = 16; o > 0; o >>= 1)
            mx = fmaxf(mx, __shfl_xor_sync(0xffffffffu, mx, o));
        float e = expf(val - mx);
        float denom = warp_sum(e);
        s_w[lane] = e / denom;
    }
    __syncthreads();

    // ---- V gather (tid<128) while zeroing logits buffer ----
    float acc = 0.f;
    if (tid < DD) {
        #pragma unroll
        for (int i = 0; i < TOPK; i++)
            acc += s_w[i] * Vmat[((size_t)n * SS + s_topi[i]) * DD + tid];
    }
    {
        float4 z = make_float4(0.f, 0.f, 0.f, 0.f);
        float4* l4 = reinterpret_cast<float4*>(logits);
        #pragma unroll
        for (int i = tid; i < SS / 4; i += 256) l4[i] = z;
    }
    __syncthreads();

    if (tid < TOPK) logits[s_topi[tid]] = s_w[tid];
    if (tid < DD)   g_summary[n * DD + tid] = acc;
    __syncthreads();

    {
        const float4* src = reinterpret_cast<const float4*>(logits);
        float4* dst = reinterpret_cast<float4*>(weights_out + (size_t)n * SS);
        #pragma unroll
        for (int i = tid; i < SS / 4; i += 256) dst[i] = src[i];
    }
}

// ---------------------------------------------------------------------------
// Fused readout GEMMs: out[n,c] = sum_d summary[n,d]*W[c,d] + bias[c]
// ---------------------------------------------------------------------------
__global__ __launch_bounds__(256) void readout_gemm(
    const float* __restrict__ Wc, const float* __restrict__ bc, float* __restrict__ outc,
    const float* __restrict__ Wr, const float* __restrict__ br, float* __restrict__ outr)
{
    const float* W;  const float* bias;  float* out;  int C;  int cTile;
    if (blockIdx.x < 32) { W = Wc; bias = bc; out = outc; C = CLS; cTile = blockIdx.x * 32; }
    else                 { W = Wr; bias = br; out = outr; C = DD;  cTile = (blockIdx.x - 32) * 32; }

    const int tid = threadIdx.x;
    const int tx  = tid & 15;
    const int ty  = tid >> 4;
    const int nTile = blockIdx.y * 32;

    __shared__ __align__(16) float As[DD][34];
    __shared__ __align__(16) float Bs[DD][34];

    {
        const int rr  = tid >> 3;
        const int k16 = tid & 7;
        const float* aRow = g_summary + (size_t)(nTile + rr) * DD + k16 * 16;
        const int cg = cTile + rr;
        const float* bRow = W + (size_t)cg * DD + k16 * 16;
        #pragma unroll
        for (int j = 0; j < 4; j++) {
            float4 va = *reinterpret_cast<const float4*>(aRow + j * 4);
            int kb = k16 * 16 + j * 4;
            As[kb + 0][rr] = va.x;
            As[kb + 1][rr] = va.y;
            As[kb + 2][rr] = va.z;
            As[kb + 3][rr] = va.w;
            float4 vb = make_float4(0.f, 0.f, 0.f, 0.f);
            if (cg < C) vb = *reinterpret_cast<const float4*>(bRow + j * 4);
            Bs[kb + 0][rr] = vb.x;
            Bs[kb + 1][rr] = vb.y;
            Bs[kb + 2][rr] = vb.z;
            Bs[kb + 3][rr] = vb.w;
        }
    }
    __syncthreads();

    float acc00 = 0.f, acc01 = 0.f, acc10 = 0.f, acc11 = 0.f;
    #pragma unroll 16
    for (int kk = 0; kk < DD; kk++) {
        float2 a = *reinterpret_cast<const float2*>(&As[kk][ty * 2]);
        float2 b = *reinterpret_cast<const float2*>(&Bs[kk][tx * 2]);
        acc00 += a.x * b.x;
        acc01 += a.x * b.y;
        acc10 += a.y * b.x;
        acc11 += a.y * b.y;
    }

    const int n0 = nTile + ty * 2;
    const int c0 = cTile + tx * 2;
    if (c0 + 0 < C) {
        float bb = bias[c0];
        out[(size_t)(n0 + 0) * C + c0] = acc00 + bb;
        out[(size_t)(n0 + 1) * C + c0] = acc10 + bb;
    }
    if (c0 + 1 < C) {
        float bb = bias[c0 + 1];
        out[(size_t)(n0 + 0) * C + c0 + 1] = acc01 + bb;
        out[(size_t)(n0 + 1) * C + c0 + 1] = acc11 + bb;
    }
}

extern "C" void kernel_launch(void* const* d_in, const int* in_sizes, int n_in,
                              void* d_out, int out_size) {
    const float* q     = (const float*)d_in[0];
    const float* Kmat  = (const float*)d_in[1];
    const float* Vmat  = (const float*)d_in[2];
    const float* W_cls = (const float*)d_in[3];
    const float* b_cls = (const float*)d_in[4];
    const float* W_rec = (const float*)d_in[5];
    const float* b_rec = (const float*)d_in[6];

    float* out = (float*)d_out;
    float* cls = out;
    float* rec = out + (size_t)NQ * CLS;
    float* wts = rec + (size_t)NQ * DD;

    attn_topk_kernel<<<NQ, 256>>>(q, Kmat, Vmat, wts);
    readout_gemm<<<dim3(36, NQ / 32), 256>>>(W_cls, b_cls, cls, W_rec, b_rec, rec);
}

// round 8
// speedup vs baseline: 1.2447x; 1.0063x over previous
#include <cuda_runtime.h>
#include <cstdint>

#define NQ   512
#define SS   2048
#define DD   128
#define TOPK 32
#define CLS  1000

__device__ float g_summary[NQ * DD];

__device__ __forceinline__ float warp_sum(float v) {
    #pragma unroll
    for (int o = 16; o > 0; o >>= 1) v += __shfl_xor_sync(0xffffffffu, v, o);
    return v;
}

__device__ __forceinline__ void cp_async16(void* smem, const void* gmem) {
    uint32_t s = (uint32_t)__cvta_generic_to_shared(smem);
    asm volatile("cp.async.cg.shared.global [%0], [%1], 16;" :: "r"(s), "l"(gmem));
}

// monotone map: float total order == uint32 order. no NaNs in this data.
__device__ __forceinline__ uint32_t fmono(float x) {
    uint32_t b = __float_as_uint(x);
    return (b & 0x80000000u) ? ~b : (b | 0x80000000u);
}

// ---------------------------------------------------------------------------
// Fused attention (unchanged from R7 — validated): K streaming via
// warp-autonomous cp.async, radix-select top-32, softmax, V gather, weights.
// ---------------------------------------------------------------------------
__global__ __launch_bounds__(256) void attn_topk_kernel(
    const float* __restrict__ q,
    const float* __restrict__ Kmat,
    const float* __restrict__ Vmat,
    float* __restrict__ weights_out)
{
    const int n    = blockIdx.x;
    const int tid  = threadIdx.x;
    const int warp = tid >> 5;
    const int lane = tid & 31;
    const int row4 = lane >> 3;
    const int g    = lane & 7;

    __shared__ __align__(16) float kring[8][2][4 * DD];  // 32 KB
    __shared__ float logits[SS];                         // 8 KB
    __shared__ uint32_t hist[4][256];                    // 4 KB
    __shared__ uint32_t sge[256];                        // 1 KB
    __shared__ uint32_t wsum[8];
    __shared__ int   s_topi[TOPK];
    __shared__ float s_w[TOPK];
    __shared__ int   eqbuf[64];
    __shared__ uint32_t s_prefix;
    __shared__ int   s_need, cA, cE;

    const float scale = 0.08838834764831845f; // 1/sqrt(128)

    float4 qf[4];
    {
        const float* qrow = q + (size_t)n * DD;
        #pragma unroll
        for (int j = 0; j < 4; j++)
            qf[j] = *reinterpret_cast<const float4*>(qrow + g * 4 + j * 32);
    }

    const float* __restrict__ Ksrc = Kmat + ((size_t)n * SS + warp * 256) * DD;
    float* __restrict__ lwarp = logits + warp * 256;

    #define K1_ISSUE(t)                                                        \
        do {                                                                   \
            float* _dst = kring[warp][(t) & 1];                                \
            const float* _src = Ksrc + (size_t)(t) * 4 * DD;                   \
            _Pragma("unroll")                                                  \
            for (int _i = 0; _i < 4; _i++)                                     \
                cp_async16(&_dst[(lane + 32 * _i) * 4],                        \
                           _src + (lane + 32 * _i) * 4);                       \
            asm volatile("cp.async.commit_group;");                            \
        } while (0)

    K1_ISSUE(0);
    K1_ISSUE(1);

    #pragma unroll 1
    for (int t = 0; t < 64; t++) {
        if (t + 1 < 64) asm volatile("cp.async.wait_group 1;");
        else            asm volatile("cp.async.wait_group 0;");
        __syncwarp();

        const float* kb = &kring[warp][t & 1][row4 * DD];
        float p = 0.f;
        #pragma unroll
        for (int j = 0; j < 4; j++) {
            float4 kv = *reinterpret_cast<const float4*>(kb + g * 4 + j * 32);
            p += qf[j].x * kv.x + qf[j].y * kv.y + qf[j].z * kv.z + qf[j].w * kv.w;
        }
        p += __shfl_xor_sync(0xffffffffu, p, 1);
        p += __shfl_xor_sync(0xffffffffu, p, 2);
        p += __shfl_xor_sync(0xffffffffu, p, 4);
        if (g == 0) lwarp[t * 4 + row4] = p * scale;
        __syncwarp();

        if (t + 2 < 64) K1_ISSUE(t + 2);
    }
    #undef K1_ISSUE

    if (tid == 0) { s_prefix = 0; s_need = TOPK; cA = 0; cE = 0; }
    __syncthreads();

    uint32_t u[8];
    #pragma unroll
    for (int j = 0; j < 8; j++) u[j] = fmono(logits[tid + 256 * j]);

    #pragma unroll 1
    for (int r = 0; r < 4; r++) {
        const int sh = 24 - 8 * r;
        #pragma unroll
        for (int b = 0; b < 4; b++) hist[b][tid] = 0;
        __syncthreads();
        const uint32_t pfx  = s_prefix;
        const int      need = s_need;
        #pragma unroll
        for (int j = 0; j < 8; j++) {
            uint32_t uu = u[j];
            bool ok = (r == 0) || ((uu >> (sh + 8)) == pfx);
            if (ok) atomicAdd(&hist[warp & 3][(uu >> sh) & 255u], 1u);
        }
        __syncthreads();
        uint32_t v = hist[0][tid] + hist[1][tid] + hist[2][tid] + hist[3][tid];
        #pragma unroll
        for (int o = 1; o < 32; o <<= 1) {
            uint32_t t2 = __shfl_down_sync(0xffffffffu, v, o);
            if (lane + o < 32) v += t2;
        }
        if (lane == 0) wsum[warp] = v;
        __syncthreads();
        uint32_t tail = 0;
        #pragma unroll
        for (int w = 0; w < 8; w++) if (w > warp) tail += wsum[w];
        uint32_t ge = v + tail;
        sge[tid] = ge;
        __syncthreads();
        uint32_t ge_next = (tid == 255) ? 0u : sge[tid + 1];
        if (ge >= (uint32_t)need && ge_next < (uint32_t)need) {
            s_prefix = (pfx << 8) | (uint32_t)tid;
            s_need   = need - (int)ge_next;
        }
        __syncthreads();
    }

    const uint32_t ustar  = s_prefix;
    const int      needEq = s_need;

    #pragma unroll
    for (int j = 0; j < 8; j++) {
        uint32_t uu = u[j];
        if (uu > ustar) {
            int p = atomicAdd(&cA, 1);
            if (p < TOPK) s_topi[p] = tid + 256 * j;
        } else if (uu == ustar) {
            int p = atomicAdd(&cE, 1);
            if (p < 64) eqbuf[p] = tid + 256 * j;
        }
    }
    __syncthreads();

    if (warp == 0) {
        const int m = min(cA, TOPK - needEq);
        int E = min(cE, 64);
        int a  = (lane      < E) ? eqbuf[lane]      : 0x7FFFFFFF;
        int b2 = (lane + 32 < E) ? eqbuf[lane + 32] : 0x7FFFFFFF;
        #pragma unroll 1
        for (int t = 0; t < needEq; t++) {
            int mn = min(a, b2);
            #pragma unroll
            for (int o = 16; o > 0; o >>= 1)
                mn = min(mn, __shfl_xor_sync(0xffffffffu, mn, o));
            if (a == mn)       a  = 0x7FFFFFFF;
            else if (b2 == mn) b2 = 0x7FFFFFFF;
            if (lane == 0) s_topi[m + t] = mn;
        }
        __syncwarp();

        float val = logits[s_topi[lane]];
        float mx = val;
        #pragma unroll
        for (int o = 16; o > 0; o >>= 1)
            mx = fmaxf(mx, __shfl_xor_sync(0xffffffffu, mx, o));
        float e = expf(val - mx);
        float denom = warp_sum(e);
        s_w[lane] = e / denom;
    }
    __syncthreads();

    float acc = 0.f;
    if (tid < DD) {
        #pragma unroll
        for (int i = 0; i < TOPK; i++)
            acc += s_w[i] * Vmat[((size_t)n * SS + s_topi[i]) * DD + tid];
    }
    {
        float4 z = make_float4(0.f, 0.f, 0.f, 0.f);
        float4* l4 = reinterpret_cast<float4*>(logits);
        #pragma unroll
        for (int i = tid; i < SS / 4; i += 256) l4[i] = z;
    }
    __syncthreads();

    if (tid < TOPK) logits[s_topi[tid]] = s_w[tid];
    if (tid < DD)   g_summary[n * DD + tid] = acc;
    __syncthreads();

    {
        const float4* src = reinterpret_cast<const float4*>(logits);
        float4* dst = reinterpret_cast<float4*>(weights_out + (size_t)n * SS);
        #pragma unroll
        for (int i = tid; i < SS / 4; i += 256) dst[i] = src[i];
    }
}

// ---------------------------------------------------------------------------
// Readout GEMMs, rebuilt: natural [row][k] smem layout (NO transpose),
// cp.async staging (no STS conflicts, no LDG wait), float4 k-chunk inner loop.
// 32x32 tiles, 2x2 micro-tile. grid (36,16): bx<32 cls, else rec.
// ---------------------------------------------------------------------------
__global__ __launch_bounds__(256) void readout_gemm(
    const float* __restrict__ Wc, const float* __restrict__ bc, float* __restrict__ outc,
    const float* __restrict__ Wr, const float* __restrict__ br, float* __restrict__ outr)
{
    const float* W;  const float* bias;  float* out;  int C;  int cTile;
    if (blockIdx.x < 32) { W = Wc; bias = bc; out = outc; C = CLS; cTile = blockIdx.x * 32; }
    else                 { W = Wr; bias = br; out = outr; C = DD;  cTile = (blockIdx.x - 32) * 32; }

    const int tid = threadIdx.x;
    const int tx  = tid & 15;       // c pair
    const int ty  = tid >> 4;       // n pair
    const int nTile = blockIdx.y * 32;

    // natural layout: row-major, 132-float row stride (33 float4, 16B aligned)
    __shared__ __align__(16) float As[32][132];
    __shared__ __align__(16) float Bs[32][132];

    // stage both tiles with cp.async: 1024 16B chunks per matrix, 4/thread
    #pragma unroll
    for (int i = 0; i < 4; i++) {
        int c  = tid + i * 256;     // 0..1023
        int rr = c >> 5;            // 0..31
        int kq = c & 31;            // 0..31 (float4 within row)
        cp_async16(&As[rr][kq * 4],
                   g_summary + (size_t)(nTile + rr) * DD + kq * 4);
        int cg = cTile + rr;
        if (cg < C) {
            cp_async16(&Bs[rr][kq * 4], W + (size_t)cg * DD + kq * 4);
        } else {
            *reinterpret_cast<float4*>(&Bs[rr][kq * 4]) =
                make_float4(0.f, 0.f, 0.f, 0.f);
        }
    }
    asm volatile("cp.async.commit_group;");
    asm volatile("cp.async.wait_group 0;");
    __syncthreads();

    const float4* A0 = reinterpret_cast<const float4*>(&As[ty * 2 + 0][0]);
    const float4* A1 = reinterpret_cast<const float4*>(&As[ty * 2 + 1][0]);
    const float4* B0 = reinterpret_cast<const float4*>(&Bs[tx * 2 + 0][0]);
    const float4* B1 = reinterpret_cast<const float4*>(&Bs[tx * 2 + 1][0]);

    float acc00 = 0.f, acc01 = 0.f, acc10 = 0.f, acc11 = 0.f;
    #pragma unroll 8
    for (int kq = 0; kq < 32; kq++) {
        float4 a0 = A0[kq];
        float4 a1 = A1[kq];
        float4 b0 = B0[kq];
        float4 b1 = B1[kq];
        acc00 += a0.x*b0.x + a0.y*b0.y + a0.z*b0.z + a0.w*b0.w;
        acc01 += a0.x*b1.x + a0.y*b1.y + a0.z*b1.z + a0.w*b1.w;
        acc10 += a1.x*b0.x + a1.y*b0.y + a1.z*b0.z + a1.w*b0.w;
        acc11 += a1.x*b1.x + a1.y*b1.y + a1.z*b1.z + a1.w*b1.w;
    }

    const int n0 = nTile + ty * 2;
    const int c0 = cTile + tx * 2;
    if (c0 + 0 < C) {
        float bb = bias[c0];
        out[(size_t)(n0 + 0) * C + c0] = acc00 + bb;
        out[(size_t)(n0 + 1) * C + c0] = acc10 + bb;
    }
    if (c0 + 1 < C) {
        float bb = bias[c0 + 1];
        out[(size_t)(n0 + 0) * C + c0 + 1] = acc01 + bb;
        out[(size_t)(n0 + 1) * C + c0 + 1] = acc11 + bb;
    }
}

extern "C" void kernel_launch(void* const* d_in, const int* in_sizes, int n_in,
                              void* d_out, int out_size) {
    const float* q     = (const float*)d_in[0];
    const float* Kmat  = (const float*)d_in[1];
    const float* Vmat  = (const float*)d_in[2];
    const float* W_cls = (const float*)d_in[3];
    const float* b_cls = (const float*)d_in[4];
    const float* W_rec = (const float*)d_in[5];
    const float* b_rec = (const float*)d_in[6];

    float* out = (float*)d_out;
    float* cls = out;
    float* rec = out + (size_t)NQ * CLS;
    float* wts = rec + (size_t)NQ * DD;

    attn_topk_kernel<<<NQ, 256>>>(q, Kmat, Vmat, wts);
    readout_gemm<<<dim3(36, NQ / 32), 256>>>(W_cls, b_cls, cls, W_rec, b_rec, rec);
}